// round 8
// baseline (speedup 1.0000x reference)
#include <cuda_runtime.h>

#define DEPTH    512
#define NPAIR    255        // pairs 0..254 real; cols 510,511 zero PE
#define ROWS     128        // rows per block
#define THREADS  128        // 4 row-groups x 32 float8 columns (one depth half)
#define HALF8    32         // float8s per half (256 floats)

struct F2 { float x, y; };

// ---------------------------------------------------------------------------
// constexpr double-precision math (compile-time only)
// ---------------------------------------------------------------------------
constexpr double kTwoPiHi = 6.283185307179586;
constexpr double kTwoPiLo = 2.4492935982947064e-16;

constexpr double d_exp(double x) {          // x in [-9.3, 0]
    double y = x / 128.0;
    double t = 1.0 + y * (1.0 + y * (1.0/2 + y * (1.0/6 + y * (1.0/24 +
               y * (1.0/120 + y * (1.0/720 + y * (1.0/5040)))))));
    for (int i = 0; i < 7; ++i) t *= t;
    return t;
}
constexpr double d_reduce(double x) {       // x >= 0 -> [-pi, pi]
    long long n = (long long)(x / kTwoPiHi + 0.5);
    return (x - (double)n * kTwoPiHi) - (double)n * kTwoPiLo;
}
constexpr double d_sin(double x) {
    double r = d_reduce(x), r2 = r * r;
    double t = 1.0 - r2 / 342.0;
    t = 1.0 - r2 / 272.0 * t;
    t = 1.0 - r2 / 210.0 * t;
    t = 1.0 - r2 / 156.0 * t;
    t = 1.0 - r2 / 110.0 * t;
    t = 1.0 - r2 / 72.0  * t;
    t = 1.0 - r2 / 42.0  * t;
    t = 1.0 - r2 / 20.0  * t;
    t = 1.0 - r2 / 6.0   * t;
    return r * t;
}
constexpr double d_cos(double x) {
    double r = d_reduce(x), r2 = r * r;
    double t = 1.0 - r2 / 380.0;
    t = 1.0 - r2 / 306.0 * t;
    t = 1.0 - r2 / 240.0 * t;
    t = 1.0 - r2 / 182.0 * t;
    t = 1.0 - r2 / 132.0 * t;
    t = 1.0 - r2 / 90.0  * t;
    t = 1.0 - r2 / 56.0  * t;
    t = 1.0 - r2 / 30.0  * t;
    t = 1.0 - r2 / 12.0  * t;
    t = 1.0 - r2 / 2.0   * t;
    return t;
}

// phasor(q * STRIDE * w_j), q in [0, COUNT), j in [0, 256). Tail j>=NPAIR -> (0, TAILC).
template<int STRIDE, int COUNT, int TAILC>
struct alignas(32) TableGen {
    F2 v[COUNT * 256];
    constexpr TableGen() : v() {
        for (int q = 0; q < COUNT; ++q) {
            for (int j = 0; j < 256; ++j) {
                F2& e = v[q * 256 + j];
                if (j >= NPAIR) { e.x = 0.f; e.y = (float)TAILC; }
                else {
                    double w = d_exp(-9.210340371976184 * (double)j / 256.0);
                    double a = (double)q * (double)STRIDE * w;
                    e.x = (float)d_sin(a);
                    e.y = (float)d_cos(a);
                }
            }
        }
    }
};

// chunk = qh*32 + ql, chunk < 1024 (L <= 131072)
__device__ const TableGen<4096, 32, 1> c_T1{};  // phasor(qh * 32*128 * w_j)
__device__ const TableGen<128,  32, 1> c_T2{};  // phasor(ql * 128    * w_j)
__device__ const TableGen<1,     4, 0> c_Tg{};  // phasor(tg * w_j); zero tail
__device__ const TableGen<4,     2, 1> c_S4{};  // slot 1 = phasor(4 * w_j)

__device__ __forceinline__ float2 cmul(float2 a, float2 b)
{   // (sin,cos) angle addition
    return make_float2(fmaf(a.x, b.y,  a.y * b.x),
                       fmaf(a.y, b.y, -a.x * b.x));
}

__device__ __forceinline__ void ldg_v8(float* v, const float* p)
{
    asm volatile("ld.global.v8.f32 {%0,%1,%2,%3,%4,%5,%6,%7}, [%8];"
                 : "=f"(v[0]), "=f"(v[1]), "=f"(v[2]), "=f"(v[3]),
                   "=f"(v[4]), "=f"(v[5]), "=f"(v[6]), "=f"(v[7])
                 : "l"(p));
}

__device__ __forceinline__ void stg_cs_v8(float* p, const float* v)
{
    asm volatile("st.global.cs.v8.f32 [%0], {%1,%2,%3,%4,%5,%6,%7,%8};"
                 :: "l"(p),
                    "f"(v[0]), "f"(v[1]), "f"(v[2]), "f"(v[3]),
                    "f"(v[4]), "f"(v[5]), "f"(v[6]), "f"(v[7])
                 : "memory");
}

// ---------------------------------------------------------------------------
// Main: 1-D grid, halves-major: bid = h * nchunks + chunk.
// Block: 128 rows x one 256-col depth half. Thread owns 8 columns
// (4 sin/cos pairs); 256-bit LDG/STG halve the L1TEX instruction stream.
// Per-SM wordlist footprint 203 KB -> L1-resident gathers.
// ---------------------------------------------------------------------------
__global__ __launch_bounds__(THREADS)
void emb_pe_kernel(const int* __restrict__ idx,
                   const float* __restrict__ wl,    // [VOCAB][512]
                   float* __restrict__ out,         // [L][512]
                   int L, int nchunks)
{
    __shared__ int sh_idx[ROWS];

    const int bid   = blockIdx.x;
    const int h     = (bid >= nchunks) ? 1 : 0;
    const int chunk = bid - h * nchunks;
    const int row0  = chunk * ROWS;
    const int nrows = min(ROWS, L - row0);
    const int tid   = threadIdx.x;

    if (tid < nrows) sh_idx[tid] = idx[row0 + tid];
    __syncthreads();

    const int tg = tid >> 5;          // row group 0..3
    const int c  = tid & 31;          // float8 column within half
    const int jb = h * 128 + 4 * c;   // first of 4 pair ids (contiguous)
    const int qh = chunk >> 5;        // < 32
    const int ql = chunk & 31;

    // Load 4 adjacent pair phasors per table (4 x F2 = 32 B each)
    const float4* t1 = reinterpret_cast<const float4*>(&c_T1.v[(qh << 8) + jb]);
    const float4* t2 = reinterpret_cast<const float4*>(&c_T2.v[(ql << 8) + jb]);
    const float4* tg4 = reinterpret_cast<const float4*>(&c_Tg.v[(tg << 8) + jb]);
    const float4* ts = reinterpret_cast<const float4*>(&c_S4.v[256 + jb]);

    float s[4], cc[4], Ss[4], Sc[4];
    #pragma unroll
    for (int p = 0; p < 2; ++p) {
        float4 A = t1[p], B = t2[p], W = tg4[p], S = ts[p];
        float2 P0 = cmul(cmul(make_float2(A.x, A.y), make_float2(B.x, B.y)),
                         make_float2(W.x, W.y));
        float2 P1 = cmul(cmul(make_float2(A.z, A.w), make_float2(B.z, B.w)),
                         make_float2(W.z, W.w));
        s[2*p]   = P0.x; cc[2*p]   = P0.y;
        s[2*p+1] = P1.x; cc[2*p+1] = P1.y;
        Ss[2*p]  = S.x;  Sc[2*p]   = S.y;
        Ss[2*p+1]= S.z;  Sc[2*p+1] = S.w;
    }

    const int colbase = h * 256 + 8 * c;          // float offset within row
    float* outp = out + (size_t)(row0 + tg) * DEPTH + colbase;
    const float* wbase = wl + colbase;

    #pragma unroll 8
    for (int r = tg; r < nrows; r += 4) {
        int token = sh_idx[r];
        float e[8], o[8];
        ldg_v8(e, wbase + (size_t)token * DEPTH);
        #pragma unroll
        for (int p = 0; p < 4; ++p) {
            o[2*p]   = e[2*p]   + s[p];
            o[2*p+1] = e[2*p+1] + cc[p];
        }
        stg_cs_v8(outp, o);
        outp += 4 * DEPTH;

        #pragma unroll
        for (int p = 0; p < 4; ++p) {
            float ns = fmaf(s[p],  Sc[p],  cc[p] * Ss[p]);
            float nc = fmaf(cc[p], Sc[p], -s[p]  * Ss[p]);
            s[p] = ns; cc[p] = nc;
        }
    }
}

extern "C" void kernel_launch(void* const* d_in, const int* in_sizes, int n_in,
                              void* d_out, int out_size)
{
    const int*   idx = (const int*)d_in[0];
    const float* wl  = (const float*)d_in[1];
    float*       out = (float*)d_out;

    int L       = in_sizes[0];
    int nchunks = (L + ROWS - 1) / ROWS;

    emb_pe_kernel<<<2 * nchunks, THREADS>>>(idx, wl, out, L, nchunks);
}

// round 9
// speedup vs baseline: 1.0531x; 1.0531x over previous
#include <cuda_runtime.h>

#define DEPTH    512
#define NPAIR    255        // pairs 0..254 real; cols 510,511 zero PE
#define ROWS     64         // rows per block
#define THREADS  128        // 2 row-groups x 64 float4 columns (one depth half)
#define HALF4    64         // float4s per half (256 floats)
#define QH_N     32
#define QL_N     64

struct F2 { float x, y; };

// ---------------------------------------------------------------------------
// constexpr double-precision math (compile-time only)
// ---------------------------------------------------------------------------
constexpr double kTwoPiHi = 6.283185307179586;
constexpr double kTwoPiLo = 2.4492935982947064e-16;

constexpr double d_exp(double x) {          // x in [-9.3, 0]
    double y = x / 128.0;
    double t = 1.0 + y * (1.0 + y * (1.0/2 + y * (1.0/6 + y * (1.0/24 +
               y * (1.0/120 + y * (1.0/720 + y * (1.0/5040)))))));
    for (int i = 0; i < 7; ++i) t *= t;
    return t;
}
constexpr double d_reduce(double x) {       // x >= 0 -> [-pi, pi]
    long long n = (long long)(x / kTwoPiHi + 0.5);
    return (x - (double)n * kTwoPiHi) - (double)n * kTwoPiLo;
}
constexpr double d_sin(double x) {
    double r = d_reduce(x), r2 = r * r;
    double t = 1.0 - r2 / 342.0;
    t = 1.0 - r2 / 272.0 * t;
    t = 1.0 - r2 / 210.0 * t;
    t = 1.0 - r2 / 156.0 * t;
    t = 1.0 - r2 / 110.0 * t;
    t = 1.0 - r2 / 72.0  * t;
    t = 1.0 - r2 / 42.0  * t;
    t = 1.0 - r2 / 20.0  * t;
    t = 1.0 - r2 / 6.0   * t;
    return r * t;
}
constexpr double d_cos(double x) {
    double r = d_reduce(x), r2 = r * r;
    double t = 1.0 - r2 / 380.0;
    t = 1.0 - r2 / 306.0 * t;
    t = 1.0 - r2 / 240.0 * t;
    t = 1.0 - r2 / 182.0 * t;
    t = 1.0 - r2 / 132.0 * t;
    t = 1.0 - r2 / 90.0  * t;
    t = 1.0 - r2 / 56.0  * t;
    t = 1.0 - r2 / 30.0  * t;
    t = 1.0 - r2 / 12.0  * t;
    t = 1.0 - r2 / 2.0   * t;
    return t;
}

// Table of phasor(q * STRIDE * w_j) for q in [0, COUNT), j in [0, 256).
// Entries with j >= NPAIR get (0, TAILC).
template<int STRIDE, int COUNT, int TAILC>
struct TableGen {
    F2 v[COUNT * 256];
    constexpr TableGen() : v() {
        for (int q = 0; q < COUNT; ++q) {
            for (int j = 0; j < 256; ++j) {
                F2& e = v[q * 256 + j];
                if (j >= NPAIR) { e.x = 0.f; e.y = (float)TAILC; }
                else {
                    double w = d_exp(-9.210340371976184 * (double)j / 256.0);
                    double a = (double)q * (double)STRIDE * w;
                    e.x = (float)d_sin(a);
                    e.y = (float)d_cos(a);
                }
            }
        }
    }
};

// Step table: phasor(2 * w_j); identity at tail so (0,0) phasors stay zero.
struct StepGen {
    F2 v[256];
    constexpr StepGen() : v() {
        for (int j = 0; j < 256; ++j) {
            if (j >= NPAIR) { v[j].x = 0.f; v[j].y = 1.f; }
            else {
                double w = d_exp(-9.210340371976184 * (double)j / 256.0);
                v[j].x = (float)d_sin(2.0 * w);
                v[j].y = (float)d_cos(2.0 * w);
            }
        }
    }
};

// All tables baked into the cubin at compile time — no init kernel.
__device__ const TableGen<4096, QH_N, 1> c_T1{};   // phasor(qh * 4096 * w_j)
__device__ const TableGen<64,   QL_N, 1> c_T2{};   // phasor(ql * 64   * w_j)
__device__ const TableGen<1,    2,    0> c_Trow{}; // phasor(tg * w_j); zero tail
__device__ const StepGen                 c_S2{};   // phasor(2 * w_j)

__device__ __forceinline__ float2 cmul(float2 a, float2 b)
{   // (sin,cos) angle addition
    return make_float2(fmaf(a.x, b.y,  a.y * b.x),
                       fmaf(a.y, b.y, -a.x * b.x));
}

__device__ __forceinline__ float2 ldF2(const F2* p)
{
    return *reinterpret_cast<const float2*>(p);
}

__device__ __forceinline__ void stg_wt_v4(float4* p, float4 v)
{   // write-through streaming store: feed DRAM continuously, avoid L2 dirty bursts
    asm volatile("st.global.wt.v4.f32 [%0], {%1,%2,%3,%4};"
                 :: "l"(p), "f"(v.x), "f"(v.y), "f"(v.z), "f"(v.w)
                 : "memory");
}

// ---------------------------------------------------------------------------
// Main: 1-D grid, halves-major: bid = h * nchunks + chunk.
// Block: 64 rows x one 256-col depth half. Per-SM wordlist footprint
// 203 KB -> L1-resident gathers.
// ---------------------------------------------------------------------------
__global__ __launch_bounds__(THREADS)
void emb_pe_kernel(const int* __restrict__ idx,
                   const float4* __restrict__ wl4,   // [VOCAB][128] float4
                   float4* __restrict__ out4,        // [L][128] float4
                   int L, int nchunks)
{
    __shared__ int sh_idx[ROWS];

    const int bid   = blockIdx.x;
    const int h     = (bid >= nchunks) ? 1 : 0;
    const int chunk = bid - h * nchunks;
    const int row0  = chunk * ROWS;
    const int nrows = min(ROWS, L - row0);
    const int tid   = threadIdx.x;

    if (tid < nrows) sh_idx[tid] = idx[row0 + tid];
    __syncthreads();

    const int tg = tid >> 6;          // 0 or 1: row parity within chunk
    const int c  = tid & 63;          // float4 column within half
    const int j0 = h * 128 + 2 * c;   // pair ids for this float4
    const int j1 = j0 + 1;
    const int qh = chunk >> 6;        // < 32
    const int ql = chunk & 63;

    // base phasor = T1[qh] * T2[ql] * Trow[tg]
    float2 P0 = cmul(cmul(ldF2(&c_T1.v[(qh << 8) + j0]),
                          ldF2(&c_T2.v[(ql << 8) + j0])),
                     ldF2(&c_Trow.v[(tg << 8) + j0]));
    float2 P1 = cmul(cmul(ldF2(&c_T1.v[(qh << 8) + j1]),
                          ldF2(&c_T2.v[(ql << 8) + j1])),
                     ldF2(&c_Trow.v[(tg << 8) + j1]));
    const float2 S0 = ldF2(&c_S2.v[j0]);
    const float2 S1 = ldF2(&c_S2.v[j1]);

    float s0 = P0.x, c0 = P0.y, s1 = P1.x, c1 = P1.y;

    const int colbase = h * HALF4 + c;
    float4* outp = out4 + (size_t)(row0 + tg) * (DEPTH / 4) + colbase;

    #pragma unroll 16
    for (int r = tg; r < nrows; r += 2) {
        int token = sh_idx[r];
        float4 e = __ldg(&wl4[token * (DEPTH / 4) + colbase]);
        float4 o;
        o.x = e.x + s0;
        o.y = e.y + c0;
        o.z = e.z + s1;
        o.w = e.w + c1;
        stg_wt_v4(outp, o);
        outp += 2 * (DEPTH / 4);

        float ns0 = fmaf(s0, S0.y,  c0 * S0.x);
        float nc0 = fmaf(c0, S0.y, -s0 * S0.x);
        float ns1 = fmaf(s1, S1.y,  c1 * S1.x);
        float nc1 = fmaf(c1, S1.y, -s1 * S1.x);
        s0 = ns0; c0 = nc0; s1 = ns1; c1 = nc1;
    }
}

extern "C" void kernel_launch(void* const* d_in, const int* in_sizes, int n_in,
                              void* d_out, int out_size)
{
    const int*   idx = (const int*)d_in[0];
    const float* wl  = (const float*)d_in[1];
    float*       out = (float*)d_out;

    int L       = in_sizes[0];
    int nchunks = (L + ROWS - 1) / ROWS;

    emb_pe_kernel<<<2 * nchunks, THREADS>>>(idx, (const float4*)wl,
                                            (float4*)out, L, nchunks);
}

// round 10
// speedup vs baseline: 1.0645x; 1.0109x over previous
#include <cuda_runtime.h>

#define DEPTH    512
#define NPAIR    255        // pairs 0..254 real; cols 510,511 zero PE
#define ROWS     64         // rows per block
#define THREADS  128        // 2 row-groups x 64 float4 columns (one depth half)
#define HALF4    64         // float4s per half (256 floats)
#define QH_N     32
#define QL_N     64

struct F2 { float x, y; };

// ---------------------------------------------------------------------------
// constexpr double-precision math (compile-time only)
// ---------------------------------------------------------------------------
constexpr double kTwoPiHi = 6.283185307179586;
constexpr double kTwoPiLo = 2.4492935982947064e-16;

constexpr double d_exp(double x) {          // x in [-9.3, 0]
    double y = x / 128.0;
    double t = 1.0 + y * (1.0 + y * (1.0/2 + y * (1.0/6 + y * (1.0/24 +
               y * (1.0/120 + y * (1.0/720 + y * (1.0/5040)))))));
    for (int i = 0; i < 7; ++i) t *= t;
    return t;
}
constexpr double d_reduce(double x) {       // x >= 0 -> [-pi, pi]
    long long n = (long long)(x / kTwoPiHi + 0.5);
    return (x - (double)n * kTwoPiHi) - (double)n * kTwoPiLo;
}
constexpr double d_sin(double x) {
    double r = d_reduce(x), r2 = r * r;
    double t = 1.0 - r2 / 342.0;
    t = 1.0 - r2 / 272.0 * t;
    t = 1.0 - r2 / 210.0 * t;
    t = 1.0 - r2 / 156.0 * t;
    t = 1.0 - r2 / 110.0 * t;
    t = 1.0 - r2 / 72.0  * t;
    t = 1.0 - r2 / 42.0  * t;
    t = 1.0 - r2 / 20.0  * t;
    t = 1.0 - r2 / 6.0   * t;
    return r * t;
}
constexpr double d_cos(double x) {
    double r = d_reduce(x), r2 = r * r;
    double t = 1.0 - r2 / 380.0;
    t = 1.0 - r2 / 306.0 * t;
    t = 1.0 - r2 / 240.0 * t;
    t = 1.0 - r2 / 182.0 * t;
    t = 1.0 - r2 / 132.0 * t;
    t = 1.0 - r2 / 90.0  * t;
    t = 1.0 - r2 / 56.0  * t;
    t = 1.0 - r2 / 30.0  * t;
    t = 1.0 - r2 / 12.0  * t;
    t = 1.0 - r2 / 2.0   * t;
    return t;
}

// Table of phasor(q * STRIDE * w_j) for q in [0, COUNT), j in [0, 256).
// Entries with j >= NPAIR get (0, TAILC).
template<int STRIDE, int COUNT, int TAILC>
struct TableGen {
    F2 v[COUNT * 256];
    constexpr TableGen() : v() {
        for (int q = 0; q < COUNT; ++q) {
            for (int j = 0; j < 256; ++j) {
                F2& e = v[q * 256 + j];
                if (j >= NPAIR) { e.x = 0.f; e.y = (float)TAILC; }
                else {
                    double w = d_exp(-9.210340371976184 * (double)j / 256.0);
                    double a = (double)q * (double)STRIDE * w;
                    e.x = (float)d_sin(a);
                    e.y = (float)d_cos(a);
                }
            }
        }
    }
};

// Step table: phasor(2 * w_j); identity at tail so (0,0) phasors stay zero.
struct StepGen {
    F2 v[256];
    constexpr StepGen() : v() {
        for (int j = 0; j < 256; ++j) {
            if (j >= NPAIR) { v[j].x = 0.f; v[j].y = 1.f; }
            else {
                double w = d_exp(-9.210340371976184 * (double)j / 256.0);
                v[j].x = (float)d_sin(2.0 * w);
                v[j].y = (float)d_cos(2.0 * w);
            }
        }
    }
};

// All tables baked into the cubin at compile time — no init kernel.
__device__ const TableGen<4096, QH_N, 1> c_T1{};   // phasor(qh * 4096 * w_j)
__device__ const TableGen<64,   QL_N, 1> c_T2{};   // phasor(ql * 64   * w_j)
__device__ const TableGen<1,    2,    0> c_Trow{}; // phasor(tg * w_j); zero tail
__device__ const StepGen                 c_S2{};   // phasor(2 * w_j)

__device__ __forceinline__ float2 cmul(float2 a, float2 b)
{   // (sin,cos) angle addition
    return make_float2(fmaf(a.x, b.y,  a.y * b.x),
                       fmaf(a.y, b.y, -a.x * b.x));
}

__device__ __forceinline__ float2 ldF2(const F2* p)
{
    return *reinterpret_cast<const float2*>(p);
}

// ---------------------------------------------------------------------------
// Main: 1-D grid, half-INTERLEAVED: h = bid & 1, chunk = bid >> 1.
// The two CTAs covering a row-chunk's two depth halves are adjacent in
// launch order -> DRAM writes are page-contiguous (full 2048 B rows).
// Block: 64 rows x one 256-col depth half.
// ---------------------------------------------------------------------------
__global__ __launch_bounds__(THREADS)
void emb_pe_kernel(const int* __restrict__ idx,
                   const float4* __restrict__ wl4,   // [VOCAB][128] float4
                   float4* __restrict__ out4,        // [L][128] float4
                   int L)
{
    __shared__ int sh_idx[ROWS];

    const int bid   = blockIdx.x;
    const int h     = bid & 1;
    const int chunk = bid >> 1;
    const int row0  = chunk * ROWS;
    const int nrows = min(ROWS, L - row0);
    const int tid   = threadIdx.x;

    if (tid < nrows) sh_idx[tid] = idx[row0 + tid];
    __syncthreads();

    const int tg = tid >> 6;          // 0 or 1: row parity within chunk
    const int c  = tid & 63;          // float4 column within half
    const int j0 = h * 128 + 2 * c;   // pair ids for this float4
    const int j1 = j0 + 1;
    const int qh = chunk >> 6;        // < 32
    const int ql = chunk & 63;

    // base phasor = T1[qh] * T2[ql] * Trow[tg]
    float2 P0 = cmul(cmul(ldF2(&c_T1.v[(qh << 8) + j0]),
                          ldF2(&c_T2.v[(ql << 8) + j0])),
                     ldF2(&c_Trow.v[(tg << 8) + j0]));
    float2 P1 = cmul(cmul(ldF2(&c_T1.v[(qh << 8) + j1]),
                          ldF2(&c_T2.v[(ql << 8) + j1])),
                     ldF2(&c_Trow.v[(tg << 8) + j1]));
    const float2 S0 = ldF2(&c_S2.v[j0]);
    const float2 S1 = ldF2(&c_S2.v[j1]);

    float s0 = P0.x, c0 = P0.y, s1 = P1.x, c1 = P1.y;

    const int colbase = h * HALF4 + c;
    float4* outp = out4 + (size_t)(row0 + tg) * (DEPTH / 4) + colbase;

    #pragma unroll 8
    for (int r = tg; r < nrows; r += 2) {
        int token = sh_idx[r];
        float4 e = __ldg(&wl4[token * (DEPTH / 4) + colbase]);
        float4 o;
        o.x = e.x + s0;
        o.y = e.y + c0;
        o.z = e.z + s1;
        o.w = e.w + c1;
        __stcs(outp, o);
        outp += 2 * (DEPTH / 4);

        float ns0 = fmaf(s0, S0.y,  c0 * S0.x);
        float nc0 = fmaf(c0, S0.y, -s0 * S0.x);
        float ns1 = fmaf(s1, S1.y,  c1 * S1.x);
        float nc1 = fmaf(c1, S1.y, -s1 * S1.x);
        s0 = ns0; c0 = nc0; s1 = ns1; c1 = nc1;
    }
}

extern "C" void kernel_launch(void* const* d_in, const int* in_sizes, int n_in,
                              void* d_out, int out_size)
{
    const int*   idx = (const int*)d_in[0];
    const float* wl  = (const float*)d_in[1];
    float*       out = (float*)d_out;

    int L       = in_sizes[0];
    int nchunks = (L + ROWS - 1) / ROWS;

    emb_pe_kernel<<<2 * nchunks, THREADS>>>(idx, (const float4*)wl,
                                            (float4*)out, L);
}

// round 11
// speedup vs baseline: 1.0821x; 1.0166x over previous
#include <cuda_runtime.h>

#define DEPTH    512
#define NPAIR    255        // pairs 0..254 real; cols 510,511 zero PE
#define ROWS     128        // rows per block (chunk)
#define THREADS  128        // 4 row-groups x 32 float4 columns (one depth quarter)
#define QTR4     32         // float4s per quarter (128 floats)
#define QH_N     32
#define QL_N     32

struct F2 { float x, y; };

// ---------------------------------------------------------------------------
// constexpr double-precision math (compile-time only)
// ---------------------------------------------------------------------------
constexpr double kTwoPiHi = 6.283185307179586;
constexpr double kTwoPiLo = 2.4492935982947064e-16;

constexpr double d_exp(double x) {          // x in [-9.3, 0]
    double y = x / 128.0;
    double t = 1.0 + y * (1.0 + y * (1.0/2 + y * (1.0/6 + y * (1.0/24 +
               y * (1.0/120 + y * (1.0/720 + y * (1.0/5040)))))));
    for (int i = 0; i < 7; ++i) t *= t;
    return t;
}
constexpr double d_reduce(double x) {       // x >= 0 -> [-pi, pi]
    long long n = (long long)(x / kTwoPiHi + 0.5);
    return (x - (double)n * kTwoPiHi) - (double)n * kTwoPiLo;
}
constexpr double d_sin(double x) {
    double r = d_reduce(x), r2 = r * r;
    double t = 1.0 - r2 / 342.0;
    t = 1.0 - r2 / 272.0 * t;
    t = 1.0 - r2 / 210.0 * t;
    t = 1.0 - r2 / 156.0 * t;
    t = 1.0 - r2 / 110.0 * t;
    t = 1.0 - r2 / 72.0  * t;
    t = 1.0 - r2 / 42.0  * t;
    t = 1.0 - r2 / 20.0  * t;
    t = 1.0 - r2 / 6.0   * t;
    return r * t;
}
constexpr double d_cos(double x) {
    double r = d_reduce(x), r2 = r * r;
    double t = 1.0 - r2 / 380.0;
    t = 1.0 - r2 / 306.0 * t;
    t = 1.0 - r2 / 240.0 * t;
    t = 1.0 - r2 / 182.0 * t;
    t = 1.0 - r2 / 132.0 * t;
    t = 1.0 - r2 / 90.0  * t;
    t = 1.0 - r2 / 56.0  * t;
    t = 1.0 - r2 / 30.0  * t;
    t = 1.0 - r2 / 12.0  * t;
    t = 1.0 - r2 / 2.0   * t;
    return t;
}

// Table of phasor(q * STRIDE * w_j) for q in [0, COUNT), j in [0, 256).
// Entries with j >= NPAIR get (0, TAILC).
template<int STRIDE, int COUNT, int TAILC>
struct TableGen {
    F2 v[COUNT * 256];
    constexpr TableGen() : v() {
        for (int q = 0; q < COUNT; ++q) {
            for (int j = 0; j < 256; ++j) {
                F2& e = v[q * 256 + j];
                if (j >= NPAIR) { e.x = 0.f; e.y = (float)TAILC; }
                else {
                    double w = d_exp(-9.210340371976184 * (double)j / 256.0);
                    double a = (double)q * (double)STRIDE * w;
                    e.x = (float)d_sin(a);
                    e.y = (float)d_cos(a);
                }
            }
        }
    }
};

// chunk = qh*32 + ql, chunk < 1024 (L <= 131072)
__device__ const TableGen<4096, QH_N, 1> c_T1{};  // phasor(qh * 32*128 * w_j)
__device__ const TableGen<128,  QL_N, 1> c_T2{};  // phasor(ql * 128    * w_j)
__device__ const TableGen<1,    4,    0> c_Tg{};  // phasor(tg * w_j); zero tail
__device__ const TableGen<4,    2,    1> c_S4{};  // slot 1 = phasor(4 * w_j)

__device__ __forceinline__ float2 cmul(float2 a, float2 b)
{   // (sin,cos) angle addition
    return make_float2(fmaf(a.x, b.y,  a.y * b.x),
                       fmaf(a.y, b.y, -a.x * b.x));
}

__device__ __forceinline__ float2 ldF2(const F2* p)
{
    return *reinterpret_cast<const float2*>(p);
}

// ---------------------------------------------------------------------------
// Main: 1-D grid, quarter-major: bid = q * nchunks + chunk.
// Block: 128 rows x one 128-col depth quarter. Per-SM wordlist footprint
// 101 KB << 228 KB L1 -> truly L1-resident gathers, minimal L2 read refills.
// ---------------------------------------------------------------------------
__global__ __launch_bounds__(THREADS)
void emb_pe_kernel(const int* __restrict__ idx,
                   const float4* __restrict__ wl4,   // [VOCAB][128] float4
                   float4* __restrict__ out4,        // [L][128] float4
                   int L, int nchunks)
{
    __shared__ int sh_idx[ROWS];

    const int bid   = blockIdx.x;
    const int q     = bid / nchunks;                  // depth quarter 0..3
    const int chunk = bid - q * nchunks;
    const int row0  = chunk * ROWS;
    const int nrows = min(ROWS, L - row0);
    const int tid   = threadIdx.x;

    if (tid < nrows) sh_idx[tid] = idx[row0 + tid];
    __syncthreads();

    const int tg = tid >> 5;          // row group 0..3
    const int c  = tid & 31;          // float4 column within quarter
    const int j0 = q * 64 + 2 * c;    // pair ids for this float4
    const int j1 = j0 + 1;
    const int qh = chunk >> 5;        // < 32
    const int ql = chunk & 31;

    // base phasor = T1[qh] * T2[ql] * Tg[tg]
    float2 P0 = cmul(cmul(ldF2(&c_T1.v[(qh << 8) + j0]),
                          ldF2(&c_T2.v[(ql << 8) + j0])),
                     ldF2(&c_Tg.v[(tg << 8) + j0]));
    float2 P1 = cmul(cmul(ldF2(&c_T1.v[(qh << 8) + j1]),
                          ldF2(&c_T2.v[(ql << 8) + j1])),
                     ldF2(&c_Tg.v[(tg << 8) + j1]));
    const float2 S0 = ldF2(&c_S4.v[256 + j0]);   // phasor(4 * w_j)
    const float2 S1 = ldF2(&c_S4.v[256 + j1]);

    float s0 = P0.x, c0 = P0.y, s1 = P1.x, c1 = P1.y;

    const int colbase = q * QTR4 + c;
    float4* outp = out4 + (size_t)(row0 + tg) * (DEPTH / 4) + colbase;

    #pragma unroll 8
    for (int r = tg; r < nrows; r += 4) {
        int token = sh_idx[r];
        float4 e = __ldg(&wl4[token * (DEPTH / 4) + colbase]);
        float4 o;
        o.x = e.x + s0;
        o.y = e.y + c0;
        o.z = e.z + s1;
        o.w = e.w + c1;
        __stcs(outp, o);
        outp += 4 * (DEPTH / 4);

        float ns0 = fmaf(s0, S0.y,  c0 * S0.x);
        float nc0 = fmaf(c0, S0.y, -s0 * S0.x);
        float ns1 = fmaf(s1, S1.y,  c1 * S1.x);
        float nc1 = fmaf(c1, S1.y, -s1 * S1.x);
        s0 = ns0; c0 = nc0; s1 = ns1; c1 = nc1;
    }
}

extern "C" void kernel_launch(void* const* d_in, const int* in_sizes, int n_in,
                              void* d_out, int out_size)
{
    const int*   idx = (const int*)d_in[0];
    const float* wl  = (const float*)d_in[1];
    float*       out = (float*)d_out;

    int L       = in_sizes[0];
    int nchunks = (L + ROWS - 1) / ROWS;

    emb_pe_kernel<<<4 * nchunks, THREADS>>>(idx, (const float4*)wl,
                                            (float4*)out, L, nchunks);
}